// round 2
// baseline (speedup 1.0000x reference)
#include <cuda_runtime.h>
#include <math.h>

#define NMAX 50000
#define EMAX 1600000
#define IN_DIM 128
#define F1 128          // HEADS*HID
#define HEADS 4
#define OUT_D 32

// ---- scratch (static __device__, no allocation) ----
__device__ float g_z1[NMAX * F1];            // layer1 linear output [N,128]
__device__ float g_el1[NMAX * HEADS];
__device__ float g_er1[NMAX * HEADS];
__device__ float g_s1[NMAX * HEADS];         // softmax denominators
__device__ float g_ex1[(size_t)EMAX * HEADS];// per-edge exp values
__device__ float g_x1[NMAX * F1];            // layer1 output accumulator (init b1)
__device__ float g_z2[NMAX * OUT_D];
__device__ float g_el2[NMAX];
__device__ float g_er2[NMAX];
__device__ float g_s2[NMAX];
__device__ float g_ex2[EMAX];

__device__ __forceinline__ float lrelu(float v) { return v > 0.f ? v : 0.2f * v; }

// ---- init: x1 accumulator = b1, out = b2, s1 = s2 = 0 ----
__global__ void k_init(const float* __restrict__ b1, const float* __restrict__ b2,
                       float* __restrict__ out, int n) {
    int i = blockIdx.x * blockDim.x + threadIdx.x;
    if (i < n * F1)     g_x1[i] = b1[i & (F1 - 1)];
    if (i < n * OUT_D)  out[i]  = b2[i & (OUT_D - 1)];
    if (i < n * HEADS)  g_s1[i] = 0.f;
    if (i < n)          g_s2[i] = 0.f;
}

// ---- GEMM1: g_z1 = h @ W1   (128 -> 128), 4 nodes per block ----
__global__ void k_gemm1(const float* __restrict__ h, const float* __restrict__ W1, int n) {
    __shared__ float xs[4][IN_DIM];
    int n0 = blockIdx.x * 4;
    int t = threadIdx.x;  // 128 threads; t = output column
#pragma unroll
    for (int j = 0; j < 4; j++) {
        int row = n0 + j;
        xs[j][t] = (row < n) ? h[(size_t)row * IN_DIM + t] : 0.f;
    }
    __syncthreads();
    float a0 = 0.f, a1 = 0.f, a2 = 0.f, a3 = 0.f;
#pragma unroll 8
    for (int k = 0; k < IN_DIM; k++) {
        float w = __ldg(&W1[k * F1 + t]);
        a0 += w * xs[0][k];
        a1 += w * xs[1][k];
        a2 += w * xs[2][k];
        a3 += w * xs[3][k];
    }
    if (n0 + 0 < n) g_z1[(size_t)(n0 + 0) * F1 + t] = a0;
    if (n0 + 1 < n) g_z1[(size_t)(n0 + 1) * F1 + t] = a1;
    if (n0 + 2 < n) g_z1[(size_t)(n0 + 2) * F1 + t] = a2;
    if (n0 + 3 < n) g_z1[(size_t)(n0 + 3) * F1 + t] = a3;
}

// ---- el/er for layer 1: one warp per node ----
__global__ void k_elr1(const float* __restrict__ al, const float* __restrict__ ar, int n) {
    int node = (blockIdx.x * blockDim.x + threadIdx.x) >> 5;
    int lane = threadIdx.x & 31;
    if (node >= n) return;
    float el[HEADS], er[HEADS];
#pragma unroll
    for (int hh = 0; hh < HEADS; hh++) {
        int c = hh * 32 + lane;
        float z = g_z1[(size_t)node * F1 + c];
        el[hh] = z * al[c];
        er[hh] = z * ar[c];
    }
#pragma unroll
    for (int off = 16; off; off >>= 1) {
#pragma unroll
        for (int hh = 0; hh < HEADS; hh++) {
            el[hh] += __shfl_xor_sync(0xffffffffu, el[hh], off);
            er[hh] += __shfl_xor_sync(0xffffffffu, er[hh], off);
        }
    }
    if (lane == 0) {
#pragma unroll
        for (int hh = 0; hh < HEADS; hh++) {
            g_el1[node * HEADS + hh] = el[hh];
            g_er1[node * HEADS + hh] = er[hh];
        }
    }
}

// ---- edge pass 1 (layer1): ex = exp(leakyrelu(el[src]+er[dst])), s[dst] += ex ----
__global__ void k_esum1(const int* __restrict__ src, const int* __restrict__ dst, int E) {
    int e = blockIdx.x * blockDim.x + threadIdx.x;
    if (e >= E) return;
    int s = src[e], d = dst[e];
    float4 el = *(const float4*)&g_el1[s * HEADS];
    float4 er = *(const float4*)&g_er1[d * HEADS];
    float4 ex;
    ex.x = __expf(lrelu(el.x + er.x));
    ex.y = __expf(lrelu(el.y + er.y));
    ex.z = __expf(lrelu(el.z + er.z));
    ex.w = __expf(lrelu(el.w + er.w));
    *(float4*)&g_ex1[(size_t)e * HEADS] = ex;
    atomicAdd(&g_s1[d * HEADS + 0], ex.x);
    atomicAdd(&g_s1[d * HEADS + 1], ex.y);
    atomicAdd(&g_s1[d * HEADS + 2], ex.z);
    atomicAdd(&g_s1[d * HEADS + 3], ex.w);
}

// ---- edge pass 2 (layer1): x1[dst] += alpha * z1[src]; thread = (edge, 4-channel group) ----
__global__ void k_eagg1(const int* __restrict__ src, const int* __restrict__ dst, int E) {
    long idx = (long)blockIdx.x * blockDim.x + threadIdx.x;
    long total = (long)E * 32;   // 32 float4 groups of 4 channels
    if (idx >= total) return;
    int e = (int)(idx >> 5);
    int t = (int)(idx & 31);     // channel group: channels 4t..4t+3
    int hh = t >> 3;             // 8 groups per head
    int s = src[e], d = dst[e];
    float alpha = __fdividef(g_ex1[(size_t)e * HEADS + hh], g_s1[d * HEADS + hh]);
    float4 z = *(const float4*)&g_z1[(size_t)s * F1 + t * 4];
    float* o = &g_x1[(size_t)d * F1 + t * 4];
    atomicAdd(o + 0, alpha * z.x);
    atomicAdd(o + 1, alpha * z.y);
    atomicAdd(o + 2, alpha * z.z);
    atomicAdd(o + 3, alpha * z.w);
}

// ---- GEMM2: g_z2 = elu(g_x1) @ W2   (128 -> 32), 16 nodes per block ----
__global__ void k_gemm2(const float* __restrict__ W2, int n) {
    __shared__ float xs[16][IN_DIM];
    int n0 = blockIdx.x * 16;
    int t = threadIdx.x;  // 128 threads
#pragma unroll
    for (int j = 0; j < 16; j++) {
        int row = n0 + j;
        float v = (row < n) ? g_x1[(size_t)row * F1 + t] : 0.f;
        xs[j][t] = v > 0.f ? v : expm1f(v);
    }
    __syncthreads();
    int c = t & 31;       // output column
    int jg = t >> 5;      // node group (4 nodes per thread)
    float acc[4] = {0.f, 0.f, 0.f, 0.f};
#pragma unroll 4
    for (int k = 0; k < IN_DIM; k++) {
        float w = __ldg(&W2[k * OUT_D + c]);
#pragma unroll
        for (int q = 0; q < 4; q++) acc[q] += w * xs[jg * 4 + q][k];
    }
#pragma unroll
    for (int q = 0; q < 4; q++) {
        int row = n0 + jg * 4 + q;
        if (row < n) g_z2[(size_t)row * OUT_D + c] = acc[q];
    }
}

// ---- el/er for layer 2: one warp per node ----
__global__ void k_elr2(const float* __restrict__ al, const float* __restrict__ ar, int n) {
    int node = (blockIdx.x * blockDim.x + threadIdx.x) >> 5;
    int lane = threadIdx.x & 31;
    if (node >= n) return;
    float z = g_z2[(size_t)node * OUT_D + lane];
    float el = z * al[lane];
    float er = z * ar[lane];
#pragma unroll
    for (int off = 16; off; off >>= 1) {
        el += __shfl_xor_sync(0xffffffffu, el, off);
        er += __shfl_xor_sync(0xffffffffu, er, off);
    }
    if (lane == 0) { g_el2[node] = el; g_er2[node] = er; }
}

// ---- edge pass 1 (layer2) ----
__global__ void k_esum2(const int* __restrict__ src, const int* __restrict__ dst, int E) {
    int e = blockIdx.x * blockDim.x + threadIdx.x;
    if (e >= E) return;
    int s = src[e], d = dst[e];
    float ex = __expf(lrelu(g_el2[s] + g_er2[d]));
    g_ex2[e] = ex;
    atomicAdd(&g_s2[d], ex);
}

// ---- edge pass 2 (layer2): out[dst] += alpha * z2[src] ----
__global__ void k_eagg2(const int* __restrict__ src, const int* __restrict__ dst,
                        float* __restrict__ out, int E) {
    long idx = (long)blockIdx.x * blockDim.x + threadIdx.x;
    long total = (long)E * 8;    // 8 float4 groups of 4 channels
    if (idx >= total) return;
    int e = (int)(idx >> 3);
    int t = (int)(idx & 7);
    int s = src[e], d = dst[e];
    float alpha = __fdividef(g_ex2[e], g_s2[d]);
    float4 z = *(const float4*)&g_z2[(size_t)s * OUT_D + t * 4];
    float* o = &out[(size_t)d * OUT_D + t * 4];
    atomicAdd(o + 0, alpha * z.x);
    atomicAdd(o + 1, alpha * z.y);
    atomicAdd(o + 2, alpha * z.z);
    atomicAdd(o + 3, alpha * z.w);
}

extern "C" void kernel_launch(void* const* d_in, const int* in_sizes, int n_in,
                              void* d_out, int out_size) {
    const float* h   = (const float*)d_in[0];
    const int*   src = (const int*)d_in[1];
    const int*   dst = (const int*)d_in[2];
    const float* W1  = (const float*)d_in[3];
    const float* al1 = (const float*)d_in[4];
    const float* ar1 = (const float*)d_in[5];
    const float* b1  = (const float*)d_in[6];
    const float* W2  = (const float*)d_in[7];
    const float* al2 = (const float*)d_in[8];
    const float* ar2 = (const float*)d_in[9];
    const float* b2  = (const float*)d_in[10];
    float* out = (float*)d_out;

    int n = in_sizes[0] / IN_DIM;
    int E = in_sizes[1];
    if (n > NMAX) n = NMAX;
    if (E > EMAX) E = EMAX;

    // init (x1 = b1, out = b2, s = 0)
    {
        int tot = n * F1;
        k_init<<<(tot + 255) / 256, 256>>>(b1, b2, out, n);
    }
    // layer 1
    k_gemm1<<<(n + 3) / 4, 128>>>(h, W1, n);
    k_elr1<<<(n + 3) / 4, 128>>>(al1, ar1, n);
    k_esum1<<<(E + 255) / 256, 256>>>(src, dst, E);
    {
        long tot = (long)E * 32;
        k_eagg1<<<(unsigned)((tot + 255) / 256), 256>>>(src, dst, E);
    }
    // layer 2
    k_gemm2<<<(n + 15) / 16, 128>>>(W2, n);
    k_elr2<<<(n + 3) / 4, 128>>>(al2, ar2, n);
    k_esum2<<<(E + 255) / 256, 256>>>(src, dst, E);
    {
        long tot = (long)E * 8;
        k_eagg2<<<(unsigned)((tot + 255) / 256), 256>>>(src, dst, out, E);
    }
}

// round 3
// speedup vs baseline: 1.7109x; 1.7109x over previous
#include <cuda_runtime.h>
#include <math.h>

#define NMAX 50000
#define EMAX 1600000
#define IN_DIM 128
#define F1 128          // HEADS*HID
#define HEADS 4
#define OUT_D 32

// ---- scratch (static __device__, no allocation) ----
__device__ float g_z1[NMAX * F1];            // layer1 linear output [N,128]
__device__ float g_el1[NMAX * HEADS];
__device__ float g_er1[NMAX * HEADS];
__device__ float g_s1[NMAX * HEADS];         // softmax denominators (layer1)
__device__ float g_msg1[NMAX * F1];          // layer1 unnormalized message accumulator
__device__ float g_z2[NMAX * OUT_D];
__device__ float g_el2[NMAX];
__device__ float g_er2[NMAX];
__device__ float g_s2[NMAX];
__device__ float g_msg2[NMAX * OUT_D];       // layer2 unnormalized message accumulator

__device__ __forceinline__ float lrelu(float v) { return v > 0.f ? v : 0.2f * v; }

__device__ __forceinline__ void red_add_v4(float* addr, float4 v) {
    asm volatile("red.global.add.v4.f32 [%0], {%1,%2,%3,%4};"
                 :: "l"(addr), "f"(v.x), "f"(v.y), "f"(v.z), "f"(v.w) : "memory");
}
__device__ __forceinline__ void red_add_f32(float* addr, float v) {
    asm volatile("red.global.add.f32 [%0], %1;" :: "l"(addr), "f"(v) : "memory");
}

// ---- init: zero accumulators ----
__global__ void k_init(int n) {
    int i = blockIdx.x * blockDim.x + threadIdx.x;
    if (i < n * F1)     g_msg1[i] = 0.f;
    if (i < n * OUT_D)  g_msg2[i] = 0.f;
    if (i < n * HEADS)  g_s1[i] = 0.f;
    if (i < n)          g_s2[i] = 0.f;
}

// ---- GEMM1: g_z1 = h @ W1   (128 -> 128), 4 nodes per block ----
__global__ void k_gemm1(const float* __restrict__ h, const float* __restrict__ W1, int n) {
    __shared__ float xs[4][IN_DIM];
    int n0 = blockIdx.x * 4;
    int t = threadIdx.x;  // 128 threads; t = output column
#pragma unroll
    for (int j = 0; j < 4; j++) {
        int row = n0 + j;
        xs[j][t] = (row < n) ? h[(size_t)row * IN_DIM + t] : 0.f;
    }
    __syncthreads();
    float a0 = 0.f, a1 = 0.f, a2 = 0.f, a3 = 0.f;
#pragma unroll 8
    for (int k = 0; k < IN_DIM; k++) {
        float w = __ldg(&W1[k * F1 + t]);
        a0 += w * xs[0][k];
        a1 += w * xs[1][k];
        a2 += w * xs[2][k];
        a3 += w * xs[3][k];
    }
    if (n0 + 0 < n) g_z1[(size_t)(n0 + 0) * F1 + t] = a0;
    if (n0 + 1 < n) g_z1[(size_t)(n0 + 1) * F1 + t] = a1;
    if (n0 + 2 < n) g_z1[(size_t)(n0 + 2) * F1 + t] = a2;
    if (n0 + 3 < n) g_z1[(size_t)(n0 + 3) * F1 + t] = a3;
}

// ---- el/er for layer 1: one warp per node ----
__global__ void k_elr1(const float* __restrict__ al, const float* __restrict__ ar, int n) {
    int node = (blockIdx.x * blockDim.x + threadIdx.x) >> 5;
    int lane = threadIdx.x & 31;
    if (node >= n) return;
    float el[HEADS], er[HEADS];
#pragma unroll
    for (int hh = 0; hh < HEADS; hh++) {
        int c = hh * 32 + lane;
        float z = g_z1[(size_t)node * F1 + c];
        el[hh] = z * al[c];
        er[hh] = z * ar[c];
    }
#pragma unroll
    for (int off = 16; off; off >>= 1) {
#pragma unroll
        for (int hh = 0; hh < HEADS; hh++) {
            el[hh] += __shfl_xor_sync(0xffffffffu, el[hh], off);
            er[hh] += __shfl_xor_sync(0xffffffffu, er[hh], off);
        }
    }
    if (lane == 0) {
#pragma unroll
        for (int hh = 0; hh < HEADS; hh++) {
            g_el1[node * HEADS + hh] = el[hh];
            g_er1[node * HEADS + hh] = er[hh];
        }
    }
}

// ---- fused edge pass (layer1): one warp per edge.
//      ex = exp(lrelu(el[src]+er[dst])); s1[dst] += ex; msg1[dst] += ex*z1[src]
__global__ void k_edge1(const int* __restrict__ src, const int* __restrict__ dst, int E) {
    int w = (blockIdx.x * blockDim.x + threadIdx.x) >> 5;
    if (w >= E) return;
    int lane = threadIdx.x & 31;
    int hh = lane >> 3;                       // 8 lanes per head
    int s = src[w], d = dst[w];
    float ex = __expf(lrelu(g_el1[s * HEADS + hh] + g_er1[d * HEADS + hh]));
    if ((lane & 7) == 0) red_add_f32(&g_s1[d * HEADS + hh], ex);
    float4 z = *(const float4*)&g_z1[(size_t)s * F1 + lane * 4];
    float4 v = make_float4(ex * z.x, ex * z.y, ex * z.z, ex * z.w);
    red_add_v4(&g_msg1[(size_t)d * F1 + lane * 4], v);
}

// ---- GEMM2: z2 = elu(msg1/s1 + b1) @ W2   (128 -> 32), 16 nodes per block ----
__global__ void k_gemm2(const float* __restrict__ W2, const float* __restrict__ b1, int n) {
    __shared__ float xs[16][IN_DIM];
    int n0 = blockIdx.x * 16;
    int t = threadIdx.x;  // 128 threads
    int hh = t >> 5;      // head for column t
#pragma unroll
    for (int j = 0; j < 16; j++) {
        int row = n0 + j;
        float v = 0.f;
        if (row < n) {
            float s = g_s1[row * HEADS + hh];
            float inv = (s > 0.f) ? __fdividef(1.f, s) : 0.f;
            v = g_msg1[(size_t)row * F1 + t] * inv + b1[t];
        }
        xs[j][t] = v > 0.f ? v : expm1f(v);
    }
    __syncthreads();
    int c = t & 31;       // output column
    int jg = t >> 5;      // node group (4 nodes per thread)
    float acc[4] = {0.f, 0.f, 0.f, 0.f};
#pragma unroll 4
    for (int k = 0; k < IN_DIM; k++) {
        float w = __ldg(&W2[k * OUT_D + c]);
#pragma unroll
        for (int q = 0; q < 4; q++) acc[q] += w * xs[jg * 4 + q][k];
    }
#pragma unroll
    for (int q = 0; q < 4; q++) {
        int row = n0 + jg * 4 + q;
        if (row < n) g_z2[(size_t)row * OUT_D + c] = acc[q];
    }
}

// ---- el/er for layer 2: one warp per node ----
__global__ void k_elr2(const float* __restrict__ al, const float* __restrict__ ar, int n) {
    int node = (blockIdx.x * blockDim.x + threadIdx.x) >> 5;
    int lane = threadIdx.x & 31;
    if (node >= n) return;
    float z = g_z2[(size_t)node * OUT_D + lane];
    float el = z * al[lane];
    float er = z * ar[lane];
#pragma unroll
    for (int off = 16; off; off >>= 1) {
        el += __shfl_xor_sync(0xffffffffu, el, off);
        er += __shfl_xor_sync(0xffffffffu, er, off);
    }
    if (lane == 0) { g_el2[node] = el; g_er2[node] = er; }
}

// ---- fused edge pass (layer2): 8 lanes per edge (4 edges per warp) ----
__global__ void k_edge2(const int* __restrict__ src, const int* __restrict__ dst, int E) {
    long idx = (long)blockIdx.x * blockDim.x + threadIdx.x;
    int e = (int)(idx >> 3);
    if (e >= E) return;
    int t = (int)(idx & 7);
    int s = src[e], d = dst[e];
    float ex = __expf(lrelu(g_el2[s] + g_er2[d]));
    if (t == 0) red_add_f32(&g_s2[d], ex);
    float4 z = *(const float4*)&g_z2[(size_t)s * OUT_D + t * 4];
    float4 v = make_float4(ex * z.x, ex * z.y, ex * z.z, ex * z.w);
    red_add_v4(&g_msg2[(size_t)d * OUT_D + t * 4], v);
}

// ---- final: out = msg2/s2 + b2 ----
__global__ void k_final(float* __restrict__ out, const float* __restrict__ b2, int n) {
    int i = blockIdx.x * blockDim.x + threadIdx.x;
    if (i >= n * OUT_D) return;
    float s = g_s2[i >> 5];
    float inv = (s > 0.f) ? __fdividef(1.f, s) : 0.f;
    out[i] = g_msg2[i] * inv + b2[i & (OUT_D - 1)];
}

extern "C" void kernel_launch(void* const* d_in, const int* in_sizes, int n_in,
                              void* d_out, int out_size) {
    const float* h   = (const float*)d_in[0];
    const int*   src = (const int*)d_in[1];
    const int*   dst = (const int*)d_in[2];
    const float* W1  = (const float*)d_in[3];
    const float* al1 = (const float*)d_in[4];
    const float* ar1 = (const float*)d_in[5];
    const float* b1  = (const float*)d_in[6];
    const float* W2  = (const float*)d_in[7];
    const float* al2 = (const float*)d_in[8];
    const float* ar2 = (const float*)d_in[9];
    const float* b2  = (const float*)d_in[10];
    float* out = (float*)d_out;

    int n = in_sizes[0] / IN_DIM;
    int E = in_sizes[1];
    if (n > NMAX) n = NMAX;
    if (E > EMAX) E = EMAX;

    k_init<<<(n * F1 + 255) / 256, 256>>>(n);
    // layer 1
    k_gemm1<<<(n + 3) / 4, 128>>>(h, W1, n);
    k_elr1<<<(n + 3) / 4, 128>>>(al1, ar1, n);
    {
        long tot = (long)E * 32;
        k_edge1<<<(unsigned)((tot + 255) / 256), 256>>>(src, dst, E);
    }
    // layer 2
    k_gemm2<<<(n + 15) / 16, 128>>>(W2, b1, n);
    k_elr2<<<(n + 3) / 4, 128>>>(al2, ar2, n);
    {
        long tot = (long)E * 8;
        k_edge2<<<(unsigned)((tot + 255) / 256), 256>>>(src, dst, E);
    }
    k_final<<<(n * OUT_D + 255) / 256, 256>>>(out, b2, n);
}

// round 4
// speedup vs baseline: 2.7099x; 1.5838x over previous
#include <cuda_runtime.h>
#include <math.h>

#define NMAX 50000
#define EMAX 1600000
#define IN_DIM 128
#define F1 128          // HEADS*HID
#define HEADS 4
#define OUT_D 32
#define SCAN_B 256      // scan block size

// ---- scratch (static __device__, no allocation) ----
__device__ float g_z1[NMAX * F1];            // layer1 linear output [N,128]
__device__ float g_el1[NMAX * HEADS];
__device__ float g_er1[NMAX * HEADS];
__device__ float g_x1[NMAX * F1];            // layer1 output (normalized + bias + elu)
__device__ float g_z2[NMAX * OUT_D];
__device__ float g_el2[NMAX];
__device__ float g_er2[NMAX];
// CSR build
__device__ int g_cnt[NMAX];
__device__ int g_rowstart[NMAX + 1];
__device__ int g_cursor[NMAX];
__device__ int g_csrsrc[EMAX];
__device__ int g_scanpart[NMAX];             // per-element inclusive scan within block
__device__ int g_blocksum[(NMAX + SCAN_B - 1) / SCAN_B];
__device__ int g_blockoff[(NMAX + SCAN_B - 1) / SCAN_B];

__device__ __forceinline__ float lrelu(float v) { return v > 0.f ? v : 0.2f * v; }
__device__ __forceinline__ float elu1(float v) { return v > 0.f ? v : expm1f(v); }

// ================= CSR build =================
__global__ void k_zero(int n) {
    int i = blockIdx.x * blockDim.x + threadIdx.x;
    if (i < n) g_cnt[i] = 0;
}

__global__ void k_hist(const int* __restrict__ dst, int E) {
    int e = blockIdx.x * blockDim.x + threadIdx.x;
    if (e < E) atomicAdd(&g_cnt[dst[e]], 1);
}

// block-local inclusive scan of counts
__global__ void k_scanA(int n) {
    __shared__ int sm[SCAN_B];
    int i = blockIdx.x * SCAN_B + threadIdx.x;
    int v = (i < n) ? g_cnt[i] : 0;
    sm[threadIdx.x] = v;
    __syncthreads();
#pragma unroll
    for (int off = 1; off < SCAN_B; off <<= 1) {
        int add = (threadIdx.x >= off) ? sm[threadIdx.x - off] : 0;
        __syncthreads();
        sm[threadIdx.x] += add;
        __syncthreads();
    }
    if (i < n) g_scanpart[i] = sm[threadIdx.x];
    if (threadIdx.x == SCAN_B - 1) g_blocksum[blockIdx.x] = sm[SCAN_B - 1];
}

// single-block exclusive scan of block sums (nb <= 256)
__global__ void k_scanB(int nb) {
    __shared__ int sm[SCAN_B];
    int t = threadIdx.x;
    int v = (t < nb) ? g_blocksum[t] : 0;
    sm[t] = v;
    __syncthreads();
#pragma unroll
    for (int off = 1; off < SCAN_B; off <<= 1) {
        int add = (t >= off) ? sm[t - off] : 0;
        __syncthreads();
        sm[t] += add;
        __syncthreads();
    }
    if (t < nb) g_blockoff[t] = sm[t] - v;   // exclusive
}

// row_start (exclusive) = blockoff + local_inclusive - cnt; cursor = row_start
__global__ void k_scanC(int n, int E) {
    int i = blockIdx.x * blockDim.x + threadIdx.x;
    if (i < n) {
        int rs = g_blockoff[i / SCAN_B] + g_scanpart[i] - g_cnt[i];
        g_rowstart[i] = rs;
        g_cursor[i] = rs;
    }
    if (i == 0) g_rowstart[n] = E;
}

__global__ void k_scatter(const int* __restrict__ src, const int* __restrict__ dst, int E) {
    int e = blockIdx.x * blockDim.x + threadIdx.x;
    if (e >= E) return;
    int pos = atomicAdd(&g_cursor[dst[e]], 1);
    g_csrsrc[pos] = src[e];
}

// ================= layer 1 =================
// GEMM1: g_z1 = h @ W1   (128 -> 128), 4 nodes per block
__global__ void k_gemm1(const float* __restrict__ h, const float* __restrict__ W1, int n) {
    __shared__ float xs[4][IN_DIM];
    int n0 = blockIdx.x * 4;
    int t = threadIdx.x;
#pragma unroll
    for (int j = 0; j < 4; j++) {
        int row = n0 + j;
        xs[j][t] = (row < n) ? h[(size_t)row * IN_DIM + t] : 0.f;
    }
    __syncthreads();
    float a0 = 0.f, a1 = 0.f, a2 = 0.f, a3 = 0.f;
#pragma unroll 8
    for (int k = 0; k < IN_DIM; k++) {
        float w = __ldg(&W1[k * F1 + t]);
        a0 += w * xs[0][k];
        a1 += w * xs[1][k];
        a2 += w * xs[2][k];
        a3 += w * xs[3][k];
    }
    if (n0 + 0 < n) g_z1[(size_t)(n0 + 0) * F1 + t] = a0;
    if (n0 + 1 < n) g_z1[(size_t)(n0 + 1) * F1 + t] = a1;
    if (n0 + 2 < n) g_z1[(size_t)(n0 + 2) * F1 + t] = a2;
    if (n0 + 3 < n) g_z1[(size_t)(n0 + 3) * F1 + t] = a3;
}

// el/er for layer 1: one warp per node
__global__ void k_elr1(const float* __restrict__ al, const float* __restrict__ ar, int n) {
    int node = (blockIdx.x * blockDim.x + threadIdx.x) >> 5;
    int lane = threadIdx.x & 31;
    if (node >= n) return;
    float el[HEADS], er[HEADS];
#pragma unroll
    for (int hh = 0; hh < HEADS; hh++) {
        int c = hh * 32 + lane;
        float z = g_z1[(size_t)node * F1 + c];
        el[hh] = z * al[c];
        er[hh] = z * ar[c];
    }
#pragma unroll
    for (int off = 16; off; off >>= 1) {
#pragma unroll
        for (int hh = 0; hh < HEADS; hh++) {
            el[hh] += __shfl_xor_sync(0xffffffffu, el[hh], off);
            er[hh] += __shfl_xor_sync(0xffffffffu, er[hh], off);
        }
    }
    if (lane == 0) {
#pragma unroll
        for (int hh = 0; hh < HEADS; hh++) {
            g_el1[node * HEADS + hh] = el[hh];
            g_er1[node * HEADS + hh] = er[hh];
        }
    }
}

// aggregation layer1: one warp per dst node; registers accumulate; fused
// softmax-normalize + bias + ELU. Output goes straight to g_x1.
__global__ void k_aggr1(const float* __restrict__ b1, int n) {
    int d = blockIdx.x * (blockDim.x >> 5) + (threadIdx.x >> 5);
    if (d >= n) return;
    int lane = threadIdx.x & 31;
    int hh = lane >> 3;
    float er = g_el1[0];  // placeholder to keep compiler happy (overwritten)
    er = g_er1[d * HEADS + hh];
    int beg = g_rowstart[d], end = g_rowstart[d + 1];
    float4 acc = make_float4(0.f, 0.f, 0.f, 0.f);
    float sacc = 0.f;
    int i = beg;
    for (; i + 1 < end; i += 2) {
        int s0 = g_csrsrc[i];
        int s1 = g_csrsrc[i + 1];
        float el0 = g_el1[s0 * HEADS + hh];
        float el1v = g_el1[s1 * HEADS + hh];
        float4 z0 = *(const float4*)&g_z1[(size_t)s0 * F1 + lane * 4];
        float4 z1 = *(const float4*)&g_z1[(size_t)s1 * F1 + lane * 4];
        float ex0 = __expf(lrelu(el0 + er));
        float ex1 = __expf(lrelu(el1v + er));
        sacc += ex0 + ex1;
        acc.x += ex0 * z0.x + ex1 * z1.x;
        acc.y += ex0 * z0.y + ex1 * z1.y;
        acc.z += ex0 * z0.z + ex1 * z1.z;
        acc.w += ex0 * z0.w + ex1 * z1.w;
    }
    if (i < end) {
        int s0 = g_csrsrc[i];
        float el0 = g_el1[s0 * HEADS + hh];
        float4 z0 = *(const float4*)&g_z1[(size_t)s0 * F1 + lane * 4];
        float ex0 = __expf(lrelu(el0 + er));
        sacc += ex0;
        acc.x += ex0 * z0.x;
        acc.y += ex0 * z0.y;
        acc.z += ex0 * z0.z;
        acc.w += ex0 * z0.w;
    }
    float inv = (sacc > 0.f) ? __fdividef(1.f, sacc) : 0.f;
    float4 bb = *(const float4*)&b1[lane * 4];
    float4 x;
    x.x = elu1(acc.x * inv + bb.x);
    x.y = elu1(acc.y * inv + bb.y);
    x.z = elu1(acc.z * inv + bb.z);
    x.w = elu1(acc.w * inv + bb.w);
    *(float4*)&g_x1[(size_t)d * F1 + lane * 4] = x;
}

// ================= layer 2 =================
// GEMM2: z2 = g_x1 @ W2   (128 -> 32), 16 nodes per block
__global__ void k_gemm2(const float* __restrict__ W2, int n) {
    __shared__ float xs[16][IN_DIM];
    int n0 = blockIdx.x * 16;
    int t = threadIdx.x;
#pragma unroll
    for (int j = 0; j < 16; j++) {
        int row = n0 + j;
        xs[j][t] = (row < n) ? g_x1[(size_t)row * F1 + t] : 0.f;
    }
    __syncthreads();
    int c = t & 31;
    int jg = t >> 5;
    float acc[4] = {0.f, 0.f, 0.f, 0.f};
#pragma unroll 4
    for (int k = 0; k < IN_DIM; k++) {
        float w = __ldg(&W2[k * OUT_D + c]);
#pragma unroll
        for (int q = 0; q < 4; q++) acc[q] += w * xs[jg * 4 + q][k];
    }
#pragma unroll
    for (int q = 0; q < 4; q++) {
        int row = n0 + jg * 4 + q;
        if (row < n) g_z2[(size_t)row * OUT_D + c] = acc[q];
    }
}

// el/er for layer 2: one warp per node
__global__ void k_elr2(const float* __restrict__ al, const float* __restrict__ ar, int n) {
    int node = (blockIdx.x * blockDim.x + threadIdx.x) >> 5;
    int lane = threadIdx.x & 31;
    if (node >= n) return;
    float z = g_z2[(size_t)node * OUT_D + lane];
    float el = z * al[lane];
    float er = z * ar[lane];
#pragma unroll
    for (int off = 16; off; off >>= 1) {
        el += __shfl_xor_sync(0xffffffffu, el, off);
        er += __shfl_xor_sync(0xffffffffu, er, off);
    }
    if (lane == 0) { g_el2[node] = el; g_er2[node] = er; }
}

// aggregation layer2: one warp per dst node; lane = output channel; fused final.
__global__ void k_aggr2(float* __restrict__ out, const float* __restrict__ b2, int n) {
    int d = blockIdx.x * (blockDim.x >> 5) + (threadIdx.x >> 5);
    if (d >= n) return;
    int lane = threadIdx.x & 31;
    float er = g_er2[d];
    int beg = g_rowstart[d], end = g_rowstart[d + 1];
    float acc = 0.f, sacc = 0.f;
    int i = beg;
    for (; i + 1 < end; i += 2) {
        int s0 = g_csrsrc[i];
        int s1 = g_csrsrc[i + 1];
        float el0 = g_el2[s0];
        float el1v = g_el2[s1];
        float z0 = g_z2[(size_t)s0 * OUT_D + lane];
        float z1 = g_z2[(size_t)s1 * OUT_D + lane];
        float ex0 = __expf(lrelu(el0 + er));
        float ex1 = __expf(lrelu(el1v + er));
        sacc += ex0 + ex1;
        acc += ex0 * z0 + ex1 * z1;
    }
    if (i < end) {
        int s0 = g_csrsrc[i];
        float el0 = g_el2[s0];
        float z0 = g_z2[(size_t)s0 * OUT_D + lane];
        float ex0 = __expf(lrelu(el0 + er));
        sacc += ex0;
        acc += ex0 * z0;
    }
    float inv = (sacc > 0.f) ? __fdividef(1.f, sacc) : 0.f;
    out[(size_t)d * OUT_D + lane] = acc * inv + b2[lane];
}

extern "C" void kernel_launch(void* const* d_in, const int* in_sizes, int n_in,
                              void* d_out, int out_size) {
    const float* h   = (const float*)d_in[0];
    const int*   src = (const int*)d_in[1];
    const int*   dst = (const int*)d_in[2];
    const float* W1  = (const float*)d_in[3];
    const float* al1 = (const float*)d_in[4];
    const float* ar1 = (const float*)d_in[5];
    const float* b1  = (const float*)d_in[6];
    const float* W2  = (const float*)d_in[7];
    const float* al2 = (const float*)d_in[8];
    const float* ar2 = (const float*)d_in[9];
    const float* b2  = (const float*)d_in[10];
    float* out = (float*)d_out;

    int n = in_sizes[0] / IN_DIM;
    int E = in_sizes[1];
    if (n > NMAX) n = NMAX;
    if (E > EMAX) E = EMAX;
    int nb = (n + SCAN_B - 1) / SCAN_B;

    // ---- CSR build ----
    k_zero<<<(n + 255) / 256, 256>>>(n);
    k_hist<<<(E + 255) / 256, 256>>>(dst, E);
    k_scanA<<<nb, SCAN_B>>>(n);
    k_scanB<<<1, SCAN_B>>>(nb);
    k_scanC<<<(n + 255) / 256, 256>>>(n, E);
    k_scatter<<<(E + 255) / 256, 256>>>(src, dst, E);

    // ---- layer 1 ----
    k_gemm1<<<(n + 3) / 4, 128>>>(h, W1, n);
    k_elr1<<<(n + 3) / 4, 128>>>(al1, ar1, n);
    k_aggr1<<<(n + 7) / 8, 256>>>(b1, n);

    // ---- layer 2 ----
    k_gemm2<<<(n + 15) / 16, 128>>>(W2, n);
    k_elr2<<<(n + 3) / 4, 128>>>(al2, ar2, n);
    k_aggr2<<<(n + 7) / 8, 256>>>(out, b2, n);
}

// round 5
// speedup vs baseline: 3.0416x; 1.1224x over previous
#include <cuda_runtime.h>
#include <math.h>

#define NMAX 50000
#define EMAX 1600000
#define IN_DIM 128
#define F1 128          // HEADS*HID
#define HEADS 4
#define OUT_D 32

// ---- scratch (static __device__, no allocation) ----
__device__ float g_z1[NMAX * F1];
__device__ float g_el1[NMAX * HEADS];
__device__ float g_er1[NMAX * HEADS];
__device__ float g_x1[NMAX * F1];            // layer1 output (normalized + bias + elu)
__device__ float g_z2[NMAX * OUT_D];
__device__ float g_el2[NMAX];
__device__ float g_er2[NMAX];
// CSR
__device__ int g_cnt[NMAX];
__device__ int g_rowstart[NMAX];
__device__ int g_cursor[NMAX];
__device__ int g_csrsrc[EMAX];
__device__ int g_total;

__device__ __forceinline__ float lrelu(float v) { return v > 0.f ? v : 0.2f * v; }
__device__ __forceinline__ float elu1(float v) { return v > 0.f ? v : expm1f(v); }

// ---- packed fp32x2 FMA (SASS FFMA2) ----
__device__ __forceinline__ unsigned long long pack2(float a, float b) {
    unsigned long long r;
    asm("mov.b64 %0, {%1, %2};" : "=l"(r) : "f"(a), "f"(b));
    return r;
}
__device__ __forceinline__ void ffma2(unsigned long long& acc, unsigned long long a,
                                      unsigned long long b) {
    asm("fma.rn.f32x2 %0, %1, %2, %0;" : "+l"(acc) : "l"(a), "l"(b));
}
__device__ __forceinline__ float hsum2(unsigned long long v) {
    float lo, hi;
    asm("mov.b64 {%0, %1}, %2;" : "=f"(lo), "=f"(hi) : "l"(v));
    return lo + hi;
}

// ================= CSR build =================
__global__ void k_zero(int n) {
    int i = blockIdx.x * blockDim.x + threadIdx.x;
    if (i < n) g_cnt[i] = 0;
    if (i == 0) g_total = 0;
}

__global__ void k_hist(const int* __restrict__ dst, int E) {
    int e = blockIdx.x * blockDim.x + threadIdx.x;
    if (e < E) atomicAdd(&g_cnt[dst[e]], 1);
}

// warp-aggregated offsets: rowstart/cursor via shuffle-scan + 1 atomic per warp
__global__ void k_offsets(int n) {
    int i = blockIdx.x * blockDim.x + threadIdx.x;
    int lane = threadIdx.x & 31;
    int c = (i < n) ? g_cnt[i] : 0;
    int inc = c;
#pragma unroll
    for (int off = 1; off < 32; off <<= 1) {
        int v = __shfl_up_sync(0xffffffffu, inc, off);
        if (lane >= off) inc += v;
    }
    int total = __shfl_sync(0xffffffffu, inc, 31);
    int base = 0;
    if (lane == 31) base = atomicAdd(&g_total, total);
    base = __shfl_sync(0xffffffffu, base, 31);
    if (i < n) {
        int rs = base + inc - c;
        g_rowstart[i] = rs;
        g_cursor[i] = rs;
    }
}

__global__ void k_scatter(const int* __restrict__ src, const int* __restrict__ dst, int E) {
    int e = blockIdx.x * blockDim.x + threadIdx.x;
    if (e >= E) return;
    int pos = atomicAdd(&g_cursor[dst[e]], 1);
    g_csrsrc[pos] = src[e];
}

// ================= layer 1 =================
// GEMM1 (16 nodes/block, FFMA2) with fused el/er warp-reduction (warp == head)
__global__ void k_gemm1(const float* __restrict__ h, const float* __restrict__ W1,
                        const float* __restrict__ al, const float* __restrict__ ar, int n) {
    __shared__ float xs[16][IN_DIM];
    int n0 = blockIdx.x * 16;
    int t = threadIdx.x;          // 128 threads; t = output column
    int lane = t & 31;
    int hh = t >> 5;              // head == warp
#pragma unroll
    for (int j = 0; j < 16; j++) {
        int row = n0 + j;
        xs[j][t] = (row < n) ? h[(size_t)row * IN_DIM + t] : 0.f;
    }
    __syncthreads();
    unsigned long long acc2[16];
#pragma unroll
    for (int j = 0; j < 16; j++) acc2[j] = 0ull;
#pragma unroll 2
    for (int k = 0; k < IN_DIM; k += 4) {
        float w0 = __ldg(&W1[(k + 0) * F1 + t]);
        float w1 = __ldg(&W1[(k + 1) * F1 + t]);
        float w2 = __ldg(&W1[(k + 2) * F1 + t]);
        float w3 = __ldg(&W1[(k + 3) * F1 + t]);
        unsigned long long wA = pack2(w0, w1);
        unsigned long long wB = pack2(w2, w3);
#pragma unroll
        for (int j = 0; j < 16; j++) {
            float4 x = *(const float4*)&xs[j][k];
            ffma2(acc2[j], wA, pack2(x.x, x.y));
            ffma2(acc2[j], wB, pack2(x.z, x.w));
        }
    }
    float av = al[t], rv = ar[t];
#pragma unroll
    for (int j = 0; j < 16; j++) {
        int row = n0 + j;
        float z = hsum2(acc2[j]);
        if (row < n) g_z1[(size_t)row * F1 + t] = z;
        float el = z * av, er = z * rv;
#pragma unroll
        for (int off = 16; off; off >>= 1) {
            el += __shfl_xor_sync(0xffffffffu, el, off);
            er += __shfl_xor_sync(0xffffffffu, er, off);
        }
        if (lane == 0 && row < n) {
            g_el1[row * HEADS + hh] = el;
            g_er1[row * HEADS + hh] = er;
        }
    }
}

// aggregation layer1: one warp per dst node; register accumulation; fused
// softmax-normalize + bias + ELU -> g_x1. Unroll x4 for MLP.
__global__ void k_aggr1(const float* __restrict__ b1, int n) {
    int d = blockIdx.x * (blockDim.x >> 5) + (threadIdx.x >> 5);
    if (d >= n) return;
    int lane = threadIdx.x & 31;
    int hh = lane >> 3;
    float er = g_er1[d * HEADS + hh];
    int beg = g_rowstart[d];
    int end = beg + g_cnt[d];
    float4 acc = make_float4(0.f, 0.f, 0.f, 0.f);
    float sacc = 0.f;
    int i = beg;
    for (; i + 3 < end; i += 4) {
        int s0 = g_csrsrc[i],     s1 = g_csrsrc[i + 1];
        int s2 = g_csrsrc[i + 2], s3 = g_csrsrc[i + 3];
        float e0 = g_el1[s0 * HEADS + hh], e1 = g_el1[s1 * HEADS + hh];
        float e2 = g_el1[s2 * HEADS + hh], e3 = g_el1[s3 * HEADS + hh];
        float4 z0 = *(const float4*)&g_z1[(size_t)s0 * F1 + lane * 4];
        float4 z1 = *(const float4*)&g_z1[(size_t)s1 * F1 + lane * 4];
        float4 z2 = *(const float4*)&g_z1[(size_t)s2 * F1 + lane * 4];
        float4 z3 = *(const float4*)&g_z1[(size_t)s3 * F1 + lane * 4];
        float x0 = __expf(lrelu(e0 + er));
        float x1 = __expf(lrelu(e1 + er));
        float x2 = __expf(lrelu(e2 + er));
        float x3 = __expf(lrelu(e3 + er));
        sacc += (x0 + x1) + (x2 + x3);
        acc.x += x0 * z0.x + x1 * z1.x + x2 * z2.x + x3 * z3.x;
        acc.y += x0 * z0.y + x1 * z1.y + x2 * z2.y + x3 * z3.y;
        acc.z += x0 * z0.z + x1 * z1.z + x2 * z2.z + x3 * z3.z;
        acc.w += x0 * z0.w + x1 * z1.w + x2 * z2.w + x3 * z3.w;
    }
    for (; i < end; i++) {
        int s0 = g_csrsrc[i];
        float e0 = g_el1[s0 * HEADS + hh];
        float4 z0 = *(const float4*)&g_z1[(size_t)s0 * F1 + lane * 4];
        float x0 = __expf(lrelu(e0 + er));
        sacc += x0;
        acc.x += x0 * z0.x; acc.y += x0 * z0.y;
        acc.z += x0 * z0.z; acc.w += x0 * z0.w;
    }
    float inv = (sacc > 0.f) ? __fdividef(1.f, sacc) : 0.f;
    float4 bb = *(const float4*)&b1[lane * 4];
    float4 x;
    x.x = elu1(acc.x * inv + bb.x);
    x.y = elu1(acc.y * inv + bb.y);
    x.z = elu1(acc.z * inv + bb.z);
    x.w = elu1(acc.w * inv + bb.w);
    *(float4*)&g_x1[(size_t)d * F1 + lane * 4] = x;
}

// ================= layer 2 =================
// GEMM2 (16 nodes/block, FFMA2) with fused el/er reduction.
// Thread layout: c = t&31 (column), jg = t>>5 (4 rows per warp).
__global__ void k_gemm2(const float* __restrict__ W2, const float* __restrict__ al,
                        const float* __restrict__ ar, int n) {
    __shared__ float xs[16][IN_DIM];
    int n0 = blockIdx.x * 16;
    int t = threadIdx.x;
    int lane = t & 31;
#pragma unroll
    for (int j = 0; j < 16; j++) {
        int row = n0 + j;
        xs[j][t] = (row < n) ? g_x1[(size_t)row * F1 + t] : 0.f;
    }
    __syncthreads();
    int c = t & 31;
    int jg = t >> 5;
    unsigned long long acc2[4] = {0ull, 0ull, 0ull, 0ull};
#pragma unroll 2
    for (int k = 0; k < IN_DIM; k += 4) {
        float w0 = __ldg(&W2[(k + 0) * OUT_D + c]);
        float w1 = __ldg(&W2[(k + 1) * OUT_D + c]);
        float w2 = __ldg(&W2[(k + 2) * OUT_D + c]);
        float w3 = __ldg(&W2[(k + 3) * OUT_D + c]);
        unsigned long long wA = pack2(w0, w1);
        unsigned long long wB = pack2(w2, w3);
#pragma unroll
        for (int q = 0; q < 4; q++) {
            float4 x = *(const float4*)&xs[jg * 4 + q][k];
            ffma2(acc2[q], wA, pack2(x.x, x.y));
            ffma2(acc2[q], wB, pack2(x.z, x.w));
        }
    }
    float av = al[c], rv = ar[c];
#pragma unroll
    for (int q = 0; q < 4; q++) {
        int row = n0 + jg * 4 + q;
        float z = hsum2(acc2[q]);
        if (row < n) g_z2[(size_t)row * OUT_D + c] = z;
        float el = z * av, er = z * rv;
#pragma unroll
        for (int off = 16; off; off >>= 1) {
            el += __shfl_xor_sync(0xffffffffu, el, off);
            er += __shfl_xor_sync(0xffffffffu, er, off);
        }
        if (lane == 0 && row < n) { g_el2[row] = el; g_er2[row] = er; }
    }
}

// aggregation layer2: one warp per dst node; lane = output channel; fused final.
__global__ void k_aggr2(float* __restrict__ out, const float* __restrict__ b2, int n) {
    int d = blockIdx.x * (blockDim.x >> 5) + (threadIdx.x >> 5);
    if (d >= n) return;
    int lane = threadIdx.x & 31;
    float er = g_er2[d];
    int beg = g_rowstart[d];
    int end = beg + g_cnt[d];
    float acc = 0.f, sacc = 0.f;
    int i = beg;
    for (; i + 3 < end; i += 4) {
        int s0 = g_csrsrc[i],     s1 = g_csrsrc[i + 1];
        int s2 = g_csrsrc[i + 2], s3 = g_csrsrc[i + 3];
        float e0 = g_el2[s0], e1 = g_el2[s1], e2 = g_el2[s2], e3 = g_el2[s3];
        float z0 = g_z2[(size_t)s0 * OUT_D + lane];
        float z1 = g_z2[(size_t)s1 * OUT_D + lane];
        float z2 = g_z2[(size_t)s2 * OUT_D + lane];
        float z3 = g_z2[(size_t)s3 * OUT_D + lane];
        float x0 = __expf(lrelu(e0 + er));
        float x1 = __expf(lrelu(e1 + er));
        float x2 = __expf(lrelu(e2 + er));
        float x3 = __expf(lrelu(e3 + er));
        sacc += (x0 + x1) + (x2 + x3);
        acc += x0 * z0 + x1 * z1 + x2 * z2 + x3 * z3;
    }
    for (; i < end; i++) {
        int s0 = g_csrsrc[i];
        float x0 = __expf(lrelu(g_el2[s0] + er));
        sacc += x0;
        acc += x0 * g_z2[(size_t)s0 * OUT_D + lane];
    }
    float inv = (sacc > 0.f) ? __fdividef(1.f, sacc) : 0.f;
    out[(size_t)d * OUT_D + lane] = acc * inv + b2[lane];
}

extern "C" void kernel_launch(void* const* d_in, const int* in_sizes, int n_in,
                              void* d_out, int out_size) {
    const float* h   = (const float*)d_in[0];
    const int*   src = (const int*)d_in[1];
    const int*   dst = (const int*)d_in[2];
    const float* W1  = (const float*)d_in[3];
    const float* al1 = (const float*)d_in[4];
    const float* ar1 = (const float*)d_in[5];
    const float* b1  = (const float*)d_in[6];
    const float* W2  = (const float*)d_in[7];
    const float* al2 = (const float*)d_in[8];
    const float* ar2 = (const float*)d_in[9];
    const float* b2  = (const float*)d_in[10];
    float* out = (float*)d_out;

    int n = in_sizes[0] / IN_DIM;
    int E = in_sizes[1];
    if (n > NMAX) n = NMAX;
    if (E > EMAX) E = EMAX;

    // ---- CSR build ----
    k_zero<<<(n + 255) / 256, 256>>>(n);
    k_hist<<<(E + 255) / 256, 256>>>(dst, E);
    k_offsets<<<(n + 255) / 256, 256>>>(n);
    k_scatter<<<(E + 255) / 256, 256>>>(src, dst, E);

    // ---- layer 1 ----
    k_gemm1<<<(n + 15) / 16, 128>>>(h, W1, al1, ar1, n);
    k_aggr1<<<(n + 7) / 8, 256>>>(b1, n);

    // ---- layer 2 ----
    k_gemm2<<<(n + 15) / 16, 128>>>(W2, al2, ar2, n);
    k_aggr2<<<(n + 7) / 8, 256>>>(out, b2, n);
}

// round 6
// speedup vs baseline: 3.0493x; 1.0025x over previous
#include <cuda_runtime.h>
#include <cuda_fp16.h>
#include <math.h>

#define NMAX 50000
#define EMAX 1600000
#define IN_DIM 128
#define F1 128          // HEADS*HID
#define HEADS 4
#define OUT_D 32

// ---- scratch (static __device__, no allocation) ----
__device__ __half g_z1h[NMAX * F1];          // fp16 copy of layer1 linear output (gather payload)
__device__ float g_el1[NMAX * HEADS];
__device__ float g_er1[NMAX * HEADS];
__device__ float g_x1[NMAX * F1];            // layer1 output (normalized + bias + elu), fp32
__device__ __half g_z2h[NMAX * OUT_D];       // fp16 copy of layer2 linear output
__device__ float g_el2[NMAX];
__device__ float g_er2[NMAX];
// CSR
__device__ int g_cnt[NMAX];
__device__ int g_rowstart[NMAX];
__device__ int g_cursor[NMAX];
__device__ int g_csrsrc[EMAX];
__device__ int g_total;

__device__ __forceinline__ float lrelu(float v) { return v > 0.f ? v : 0.2f * v; }
__device__ __forceinline__ float elu1(float v) { return v > 0.f ? v : expm1f(v); }

// ---- packed fp32x2 FMA (SASS FFMA2) ----
__device__ __forceinline__ unsigned long long pack2(float a, float b) {
    unsigned long long r;
    asm("mov.b64 %0, {%1, %2};" : "=l"(r) : "f"(a), "f"(b));
    return r;
}
__device__ __forceinline__ void ffma2(unsigned long long& acc, unsigned long long a,
                                      unsigned long long b) {
    asm("fma.rn.f32x2 %0, %1, %2, %0;" : "+l"(acc) : "l"(a), "l"(b));
}
__device__ __forceinline__ float hsum2(unsigned long long v) {
    float lo, hi;
    asm("mov.b64 {%0, %1}, %2;" : "=f"(lo), "=f"(hi) : "l"(v));
    return lo + hi;
}

// ================= CSR build =================
__global__ void k_zero(int n) {
    int i = blockIdx.x * blockDim.x + threadIdx.x;
    if (i < n) g_cnt[i] = 0;
    if (i == 0) g_total = 0;
}

// 4 edges per thread, int4 loads, independent RED atomics
__global__ void k_hist(const int* __restrict__ dst, int E) {
    int e = (blockIdx.x * blockDim.x + threadIdx.x) * 4;
    if (e + 3 < E) {
        int4 d4 = *(const int4*)&dst[e];
        atomicAdd(&g_cnt[d4.x], 1);
        atomicAdd(&g_cnt[d4.y], 1);
        atomicAdd(&g_cnt[d4.z], 1);
        atomicAdd(&g_cnt[d4.w], 1);
    } else {
        for (int r = 0; r < 4; r++)
            if (e + r < E) atomicAdd(&g_cnt[dst[e + r]], 1);
    }
}

// warp-aggregated offsets: shuffle-scan + 1 atomic per warp
__global__ void k_offsets(int n) {
    int i = blockIdx.x * blockDim.x + threadIdx.x;
    int lane = threadIdx.x & 31;
    int c = (i < n) ? g_cnt[i] : 0;
    int inc = c;
#pragma unroll
    for (int off = 1; off < 32; off <<= 1) {
        int v = __shfl_up_sync(0xffffffffu, inc, off);
        if (lane >= off) inc += v;
    }
    int total = __shfl_sync(0xffffffffu, inc, 31);
    int base = 0;
    if (lane == 31) base = atomicAdd(&g_total, total);
    base = __shfl_sync(0xffffffffu, base, 31);
    if (i < n) {
        int rs = base + inc - c;
        g_rowstart[i] = rs;
        g_cursor[i] = rs;
    }
}

// 4 edges per thread: batched loads, 4 independent atomics, then 4 stores
__global__ void k_scatter(const int* __restrict__ src, const int* __restrict__ dst, int E) {
    int e = (blockIdx.x * blockDim.x + threadIdx.x) * 4;
    if (e + 3 < E) {
        int4 d4 = *(const int4*)&dst[e];
        int4 s4 = *(const int4*)&src[e];
        int p0 = atomicAdd(&g_cursor[d4.x], 1);
        int p1 = atomicAdd(&g_cursor[d4.y], 1);
        int p2 = atomicAdd(&g_cursor[d4.z], 1);
        int p3 = atomicAdd(&g_cursor[d4.w], 1);
        g_csrsrc[p0] = s4.x;
        g_csrsrc[p1] = s4.y;
        g_csrsrc[p2] = s4.z;
        g_csrsrc[p3] = s4.w;
    } else {
        for (int r = 0; r < 4; r++) {
            if (e + r < E) {
                int pos = atomicAdd(&g_cursor[dst[e + r]], 1);
                g_csrsrc[pos] = src[e + r];
            }
        }
    }
}

// ================= layer 1 =================
// GEMM1 (16 nodes/block, FFMA2), fused el/er warp-reduction, fp16 z output
__global__ void k_gemm1(const float* __restrict__ h, const float* __restrict__ W1,
                        const float* __restrict__ al, const float* __restrict__ ar, int n) {
    __shared__ float xs[16][IN_DIM];
    int n0 = blockIdx.x * 16;
    int t = threadIdx.x;          // 128 threads; t = output column
    int lane = t & 31;
    int hh = t >> 5;              // head == warp
#pragma unroll
    for (int j = 0; j < 16; j++) {
        int row = n0 + j;
        xs[j][t] = (row < n) ? h[(size_t)row * IN_DIM + t] : 0.f;
    }
    __syncthreads();
    unsigned long long acc2[16];
#pragma unroll
    for (int j = 0; j < 16; j++) acc2[j] = 0ull;
#pragma unroll 2
    for (int k = 0; k < IN_DIM; k += 4) {
        float w0 = __ldg(&W1[(k + 0) * F1 + t]);
        float w1 = __ldg(&W1[(k + 1) * F1 + t]);
        float w2 = __ldg(&W1[(k + 2) * F1 + t]);
        float w3 = __ldg(&W1[(k + 3) * F1 + t]);
        unsigned long long wA = pack2(w0, w1);
        unsigned long long wB = pack2(w2, w3);
#pragma unroll
        for (int j = 0; j < 16; j++) {
            float4 x = *(const float4*)&xs[j][k];
            ffma2(acc2[j], wA, pack2(x.x, x.y));
            ffma2(acc2[j], wB, pack2(x.z, x.w));
        }
    }
    float av = al[t], rv = ar[t];
#pragma unroll
    for (int j = 0; j < 16; j++) {
        int row = n0 + j;
        float z = hsum2(acc2[j]);
        if (row < n) g_z1h[(size_t)row * F1 + t] = __float2half_rn(z);
        float el = z * av, er = z * rv;
#pragma unroll
        for (int off = 16; off; off >>= 1) {
            el += __shfl_xor_sync(0xffffffffu, el, off);
            er += __shfl_xor_sync(0xffffffffu, er, off);
        }
        if (lane == 0 && row < n) {
            g_el1[row * HEADS + hh] = el;
            g_er1[row * HEADS + hh] = er;
        }
    }
}

// aggregation layer1: one warp per dst node; fp16 gathers, fp32 accumulation;
// fused softmax-normalize + bias + ELU -> g_x1
__global__ void k_aggr1(const float* __restrict__ b1, int n) {
    int d = blockIdx.x * (blockDim.x >> 5) + (threadIdx.x >> 5);
    if (d >= n) return;
    int lane = threadIdx.x & 31;
    int hh = lane >> 3;
    float er = g_er1[d * HEADS + hh];
    int beg = g_rowstart[d];
    int end = beg + g_cnt[d];
    float4 acc = make_float4(0.f, 0.f, 0.f, 0.f);
    float sacc = 0.f;
    int i = beg;
    for (; i + 3 < end; i += 4) {
        int s0 = g_csrsrc[i],     s1 = g_csrsrc[i + 1];
        int s2 = g_csrsrc[i + 2], s3 = g_csrsrc[i + 3];
        float e0 = g_el1[s0 * HEADS + hh], e1 = g_el1[s1 * HEADS + hh];
        float e2 = g_el1[s2 * HEADS + hh], e3 = g_el1[s3 * HEADS + hh];
        uint2 u0 = *(const uint2*)&g_z1h[(size_t)s0 * F1 + lane * 4];
        uint2 u1 = *(const uint2*)&g_z1h[(size_t)s1 * F1 + lane * 4];
        uint2 u2 = *(const uint2*)&g_z1h[(size_t)s2 * F1 + lane * 4];
        uint2 u3 = *(const uint2*)&g_z1h[(size_t)s3 * F1 + lane * 4];
        float x0 = __expf(lrelu(e0 + er));
        float x1 = __expf(lrelu(e1 + er));
        float x2 = __expf(lrelu(e2 + er));
        float x3 = __expf(lrelu(e3 + er));
        sacc += (x0 + x1) + (x2 + x3);
        float2 a0 = __half22float2(*(__half2*)&u0.x), b0 = __half22float2(*(__half2*)&u0.y);
        float2 a1 = __half22float2(*(__half2*)&u1.x), b1v = __half22float2(*(__half2*)&u1.y);
        float2 a2 = __half22float2(*(__half2*)&u2.x), b2v = __half22float2(*(__half2*)&u2.y);
        float2 a3 = __half22float2(*(__half2*)&u3.x), b3v = __half22float2(*(__half2*)&u3.y);
        acc.x += x0 * a0.x + x1 * a1.x + x2 * a2.x + x3 * a3.x;
        acc.y += x0 * a0.y + x1 * a1.y + x2 * a2.y + x3 * a3.y;
        acc.z += x0 * b0.x + x1 * b1v.x + x2 * b2v.x + x3 * b3v.x;
        acc.w += x0 * b0.y + x1 * b1v.y + x2 * b2v.y + x3 * b3v.y;
    }
    for (; i < end; i++) {
        int s0 = g_csrsrc[i];
        float e0 = g_el1[s0 * HEADS + hh];
        uint2 u0 = *(const uint2*)&g_z1h[(size_t)s0 * F1 + lane * 4];
        float x0 = __expf(lrelu(e0 + er));
        sacc += x0;
        float2 a0 = __half22float2(*(__half2*)&u0.x), b0 = __half22float2(*(__half2*)&u0.y);
        acc.x += x0 * a0.x; acc.y += x0 * a0.y;
        acc.z += x0 * b0.x; acc.w += x0 * b0.y;
    }
    float inv = (sacc > 0.f) ? __fdividef(1.f, sacc) : 0.f;
    float4 bb = *(const float4*)&b1[lane * 4];
    float4 x;
    x.x = elu1(acc.x * inv + bb.x);
    x.y = elu1(acc.y * inv + bb.y);
    x.z = elu1(acc.z * inv + bb.z);
    x.w = elu1(acc.w * inv + bb.w);
    *(float4*)&g_x1[(size_t)d * F1 + lane * 4] = x;
}

// ================= layer 2 =================
// GEMM2 (16 nodes/block, FFMA2), fused el/er reduction, fp16 z output
__global__ void k_gemm2(const float* __restrict__ W2, const float* __restrict__ al,
                        const float* __restrict__ ar, int n) {
    __shared__ float xs[16][IN_DIM];
    int n0 = blockIdx.x * 16;
    int t = threadIdx.x;
    int lane = t & 31;
#pragma unroll
    for (int j = 0; j < 16; j++) {
        int row = n0 + j;
        xs[j][t] = (row < n) ? g_x1[(size_t)row * F1 + t] : 0.f;
    }
    __syncthreads();
    int c = t & 31;
    int jg = t >> 5;
    unsigned long long acc2[4] = {0ull, 0ull, 0ull, 0ull};
#pragma unroll 2
    for (int k = 0; k < IN_DIM; k += 4) {
        float w0 = __ldg(&W2[(k + 0) * OUT_D + c]);
        float w1 = __ldg(&W2[(k + 1) * OUT_D + c]);
        float w2 = __ldg(&W2[(k + 2) * OUT_D + c]);
        float w3 = __ldg(&W2[(k + 3) * OUT_D + c]);
        unsigned long long wA = pack2(w0, w1);
        unsigned long long wB = pack2(w2, w3);
#pragma unroll
        for (int q = 0; q < 4; q++) {
            float4 x = *(const float4*)&xs[jg * 4 + q][k];
            ffma2(acc2[q], wA, pack2(x.x, x.y));
            ffma2(acc2[q], wB, pack2(x.z, x.w));
        }
    }
    float av = al[c], rv = ar[c];
#pragma unroll
    for (int q = 0; q < 4; q++) {
        int row = n0 + jg * 4 + q;
        float z = hsum2(acc2[q]);
        if (row < n) g_z2h[(size_t)row * OUT_D + c] = __float2half_rn(z);
        float el = z * av, er = z * rv;
#pragma unroll
        for (int off = 16; off; off >>= 1) {
            el += __shfl_xor_sync(0xffffffffu, el, off);
            er += __shfl_xor_sync(0xffffffffu, er, off);
        }
        if (lane == 0 && row < n) { g_el2[row] = el; g_er2[row] = er; }
    }
}

// aggregation layer2: one warp per dst node; lane = output channel; fused final.
__global__ void k_aggr2(float* __restrict__ out, const float* __restrict__ b2, int n) {
    int d = blockIdx.x * (blockDim.x >> 5) + (threadIdx.x >> 5);
    if (d >= n) return;
    int lane = threadIdx.x & 31;
    float er = g_er2[d];
    int beg = g_rowstart[d];
    int end = beg + g_cnt[d];
    float acc = 0.f, sacc = 0.f;
    int i = beg;
    for (; i + 3 < end; i += 4) {
        int s0 = g_csrsrc[i],     s1 = g_csrsrc[i + 1];
        int s2 = g_csrsrc[i + 2], s3 = g_csrsrc[i + 3];
        float e0 = g_el2[s0], e1 = g_el2[s1], e2 = g_el2[s2], e3 = g_el2[s3];
        float z0 = __half2float(g_z2h[(size_t)s0 * OUT_D + lane]);
        float z1 = __half2float(g_z2h[(size_t)s1 * OUT_D + lane]);
        float z2 = __half2float(g_z2h[(size_t)s2 * OUT_D + lane]);
        float z3 = __half2float(g_z2h[(size_t)s3 * OUT_D + lane]);
        float x0 = __expf(lrelu(e0 + er));
        float x1 = __expf(lrelu(e1 + er));
        float x2 = __expf(lrelu(e2 + er));
        float x3 = __expf(lrelu(e3 + er));
        sacc += (x0 + x1) + (x2 + x3);
        acc += x0 * z0 + x1 * z1 + x2 * z2 + x3 * z3;
    }
    for (; i < end; i++) {
        int s0 = g_csrsrc[i];
        float x0 = __expf(lrelu(g_el2[s0] + er));
        sacc += x0;
        acc += x0 * __half2float(g_z2h[(size_t)s0 * OUT_D + lane]);
    }
    float inv = (sacc > 0.f) ? __fdividef(1.f, sacc) : 0.f;
    out[(size_t)d * OUT_D + lane] = acc * inv + b2[lane];
}

extern "C" void kernel_launch(void* const* d_in, const int* in_sizes, int n_in,
                              void* d_out, int out_size) {
    const float* h   = (const float*)d_in[0];
    const int*   src = (const int*)d_in[1];
    const int*   dst = (const int*)d_in[2];
    const float* W1  = (const float*)d_in[3];
    const float* al1 = (const float*)d_in[4];
    const float* ar1 = (const float*)d_in[5];
    const float* b1  = (const float*)d_in[6];
    const float* W2  = (const float*)d_in[7];
    const float* al2 = (const float*)d_in[8];
    const float* ar2 = (const float*)d_in[9];
    const float* b2  = (const float*)d_in[10];
    float* out = (float*)d_out;

    int n = in_sizes[0] / IN_DIM;
    int E = in_sizes[1];
    if (n > NMAX) n = NMAX;
    if (E > EMAX) E = EMAX;

    // ---- CSR build ----
    k_zero<<<(n + 255) / 256, 256>>>(n);
    k_hist<<<(E / 4 + 255) / 256, 256>>>(dst, E);
    k_offsets<<<(n + 255) / 256, 256>>>(n);
    k_scatter<<<(E / 4 + 255) / 256, 256>>>(src, dst, E);

    // ---- layer 1 ----
    k_gemm1<<<(n + 15) / 16, 128>>>(h, W1, al1, ar1, n);
    k_aggr1<<<(n + 7) / 8, 256>>>(b1, n);

    // ---- layer 2 ----
    k_gemm2<<<(n + 15) / 16, 128>>>(W2, al2, ar2, n);
    k_aggr2<<<(n + 7) / 8, 256>>>(out, b2, n);
}

// round 7
// speedup vs baseline: 3.1657x; 1.0382x over previous
#include <cuda_runtime.h>
#include <cuda_fp16.h>
#include <math.h>

#define NMAX 50000
#define EMAX 1600000
#define IN_DIM 128
#define F1 128          // HEADS*HID
#define HEADS 4
#define OUT_D 32

// ---- scratch (static __device__, no allocation) ----
__device__ __half g_z1h[NMAX * F1];          // fp16 layer1 linear output (gather payload)
__device__ float g_el1[NMAX * HEADS];
__device__ float g_er1[NMAX * HEADS];
__device__ float g_x1[NMAX * F1];            // layer1 output (normalized + bias + elu)
__device__ __half g_z2h[NMAX * OUT_D];       // fp16 layer2 linear output
__device__ float g_el2[NMAX];
__device__ float g_er2[NMAX];
// CSR
__device__ int g_cnt[NMAX];
__device__ int g_rowstart[NMAX];
__device__ int g_rank[EMAX];
__device__ int g_csrsrc[EMAX];
__device__ int g_total;

__device__ __forceinline__ float lrelu(float v) { return v > 0.f ? v : 0.2f * v; }
__device__ __forceinline__ float elu1(float v) { return v > 0.f ? v : expm1f(v); }

// ---- packed fp32x2 FMA (SASS FFMA2) ----
__device__ __forceinline__ unsigned long long pack2(float a, float b) {
    unsigned long long r;
    asm("mov.b64 %0, {%1, %2};" : "=l"(r) : "f"(a), "f"(b));
    return r;
}
__device__ __forceinline__ void ffma2(unsigned long long& acc, unsigned long long a,
                                      unsigned long long b) {
    asm("fma.rn.f32x2 %0, %1, %2, %0;" : "+l"(acc) : "l"(a), "l"(b));
}
__device__ __forceinline__ float hsum2(unsigned long long v) {
    float lo, hi;
    asm("mov.b64 {%0, %1}, %2;" : "=f"(lo), "=f"(hi) : "l"(v));
    return lo + hi;
}

// ================= CSR build =================
__global__ void k_zero(int n) {
    int i = blockIdx.x * blockDim.x + threadIdx.x;
    if (i < n) g_cnt[i] = 0;
    if (i == 0) g_total = 0;
}

// hist that also records each edge's rank within its dst bucket (atomicAdd return)
__global__ void k_hist(const int* __restrict__ dst, int E) {
    int e = (blockIdx.x * blockDim.x + threadIdx.x) * 4;
    if (e + 3 < E) {
        int4 d4 = *(const int4*)&dst[e];
        int4 r4;
        r4.x = atomicAdd(&g_cnt[d4.x], 1);
        r4.y = atomicAdd(&g_cnt[d4.y], 1);
        r4.z = atomicAdd(&g_cnt[d4.z], 1);
        r4.w = atomicAdd(&g_cnt[d4.w], 1);
        *(int4*)&g_rank[e] = r4;
    } else {
        for (int r = 0; r < 4; r++)
            if (e + r < E) g_rank[e + r] = atomicAdd(&g_cnt[dst[e + r]], 1);
    }
}

// warp-aggregated offsets: shuffle-scan + 1 atomic per warp
__global__ void k_offsets(int n) {
    int i = blockIdx.x * blockDim.x + threadIdx.x;
    int lane = threadIdx.x & 31;
    int c = (i < n) ? g_cnt[i] : 0;
    int inc = c;
#pragma unroll
    for (int off = 1; off < 32; off <<= 1) {
        int v = __shfl_up_sync(0xffffffffu, inc, off);
        if (lane >= off) inc += v;
    }
    int total = __shfl_sync(0xffffffffu, inc, 31);
    int base = 0;
    if (lane == 31) base = atomicAdd(&g_total, total);
    base = __shfl_sync(0xffffffffu, base, 31);
    if (i < n) g_rowstart[i] = base + inc - c;
}

// atomic-free scatter: pos = rowstart[dst] + rank
__global__ void k_scatter(const int* __restrict__ src, const int* __restrict__ dst, int E) {
    int e = (blockIdx.x * blockDim.x + threadIdx.x) * 4;
    if (e + 3 < E) {
        int4 d4 = *(const int4*)&dst[e];
        int4 s4 = *(const int4*)&src[e];
        int4 r4 = *(const int4*)&g_rank[e];
        int p0 = g_rowstart[d4.x] + r4.x;
        int p1 = g_rowstart[d4.y] + r4.y;
        int p2 = g_rowstart[d4.z] + r4.z;
        int p3 = g_rowstart[d4.w] + r4.w;
        g_csrsrc[p0] = s4.x;
        g_csrsrc[p1] = s4.y;
        g_csrsrc[p2] = s4.z;
        g_csrsrc[p3] = s4.w;
    } else {
        for (int r = 0; r < 4; r++) {
            if (e + r < E)
                g_csrsrc[g_rowstart[dst[e + r]] + g_rank[e + r]] = src[e + r];
        }
    }
}

// ================= layer 1 =================
// GEMM1 (16 nodes/block, FFMA2), fused el/er warp-reduction, fp16 z output
__global__ void k_gemm1(const float* __restrict__ h, const float* __restrict__ W1,
                        const float* __restrict__ al, const float* __restrict__ ar, int n) {
    __shared__ float xs[16][IN_DIM];
    int n0 = blockIdx.x * 16;
    int t = threadIdx.x;
    int lane = t & 31;
    int hh = t >> 5;
#pragma unroll
    for (int j = 0; j < 16; j++) {
        int row = n0 + j;
        xs[j][t] = (row < n) ? h[(size_t)row * IN_DIM + t] : 0.f;
    }
    __syncthreads();
    unsigned long long acc2[16];
#pragma unroll
    for (int j = 0; j < 16; j++) acc2[j] = 0ull;
#pragma unroll 2
    for (int k = 0; k < IN_DIM; k += 4) {
        float w0 = __ldg(&W1[(k + 0) * F1 + t]);
        float w1 = __ldg(&W1[(k + 1) * F1 + t]);
        float w2 = __ldg(&W1[(k + 2) * F1 + t]);
        float w3 = __ldg(&W1[(k + 3) * F1 + t]);
        unsigned long long wA = pack2(w0, w1);
        unsigned long long wB = pack2(w2, w3);
#pragma unroll
        for (int j = 0; j < 16; j++) {
            float4 x = *(const float4*)&xs[j][k];
            ffma2(acc2[j], wA, pack2(x.x, x.y));
            ffma2(acc2[j], wB, pack2(x.z, x.w));
        }
    }
    float av = al[t], rv = ar[t];
#pragma unroll
    for (int j = 0; j < 16; j++) {
        int row = n0 + j;
        float z = hsum2(acc2[j]);
        if (row < n) g_z1h[(size_t)row * F1 + t] = __float2half_rn(z);
        float el = z * av, er = z * rv;
#pragma unroll
        for (int off = 16; off; off >>= 1) {
            el += __shfl_xor_sync(0xffffffffu, el, off);
            er += __shfl_xor_sync(0xffffffffu, er, off);
        }
        if (lane == 0 && row < n) {
            g_el1[row * HEADS + hh] = el;
            g_er1[row * HEADS + hh] = er;
        }
    }
}

// aggregation layer1: one warp per dst node; fp16 gathers, fp32 accumulation
__global__ void k_aggr1(const float* __restrict__ b1, int n) {
    int d = blockIdx.x * (blockDim.x >> 5) + (threadIdx.x >> 5);
    if (d >= n) return;
    int lane = threadIdx.x & 31;
    int hh = lane >> 3;
    float er = g_er1[d * HEADS + hh];
    int beg = g_rowstart[d];
    int end = beg + g_cnt[d];
    float4 acc = make_float4(0.f, 0.f, 0.f, 0.f);
    float sacc = 0.f;
    int i = beg;
    for (; i + 3 < end; i += 4) {
        int s0 = g_csrsrc[i],     s1 = g_csrsrc[i + 1];
        int s2 = g_csrsrc[i + 2], s3 = g_csrsrc[i + 3];
        float e0 = g_el1[s0 * HEADS + hh], e1 = g_el1[s1 * HEADS + hh];
        float e2 = g_el1[s2 * HEADS + hh], e3 = g_el1[s3 * HEADS + hh];
        uint2 u0 = *(const uint2*)&g_z1h[(size_t)s0 * F1 + lane * 4];
        uint2 u1 = *(const uint2*)&g_z1h[(size_t)s1 * F1 + lane * 4];
        uint2 u2 = *(const uint2*)&g_z1h[(size_t)s2 * F1 + lane * 4];
        uint2 u3 = *(const uint2*)&g_z1h[(size_t)s3 * F1 + lane * 4];
        float x0 = __expf(lrelu(e0 + er));
        float x1 = __expf(lrelu(e1 + er));
        float x2 = __expf(lrelu(e2 + er));
        float x3 = __expf(lrelu(e3 + er));
        sacc += (x0 + x1) + (x2 + x3);
        float2 a0 = __half22float2(*(__half2*)&u0.x), b0 = __half22float2(*(__half2*)&u0.y);
        float2 a1 = __half22float2(*(__half2*)&u1.x), b1v = __half22float2(*(__half2*)&u1.y);
        float2 a2 = __half22float2(*(__half2*)&u2.x), b2v = __half22float2(*(__half2*)&u2.y);
        float2 a3 = __half22float2(*(__half2*)&u3.x), b3v = __half22float2(*(__half2*)&u3.y);
        acc.x += x0 * a0.x + x1 * a1.x + x2 * a2.x + x3 * a3.x;
        acc.y += x0 * a0.y + x1 * a1.y + x2 * a2.y + x3 * a3.y;
        acc.z += x0 * b0.x + x1 * b1v.x + x2 * b2v.x + x3 * b3v.x;
        acc.w += x0 * b0.y + x1 * b1v.y + x2 * b2v.y + x3 * b3v.y;
    }
    for (; i < end; i++) {
        int s0 = g_csrsrc[i];
        float e0 = g_el1[s0 * HEADS + hh];
        uint2 u0 = *(const uint2*)&g_z1h[(size_t)s0 * F1 + lane * 4];
        float x0 = __expf(lrelu(e0 + er));
        sacc += x0;
        float2 a0 = __half22float2(*(__half2*)&u0.x), b0 = __half22float2(*(__half2*)&u0.y);
        acc.x += x0 * a0.x; acc.y += x0 * a0.y;
        acc.z += x0 * b0.x; acc.w += x0 * b0.y;
    }
    float inv = (sacc > 0.f) ? __fdividef(1.f, sacc) : 0.f;
    float4 bb = *(const float4*)&b1[lane * 4];
    float4 x;
    x.x = elu1(acc.x * inv + bb.x);
    x.y = elu1(acc.y * inv + bb.y);
    x.z = elu1(acc.z * inv + bb.z);
    x.w = elu1(acc.w * inv + bb.w);
    *(float4*)&g_x1[(size_t)d * F1 + lane * 4] = x;
}

// ================= layer 2 =================
__global__ void k_gemm2(const float* __restrict__ W2, const float* __restrict__ al,
                        const float* __restrict__ ar, int n) {
    __shared__ float xs[16][IN_DIM];
    int n0 = blockIdx.x * 16;
    int t = threadIdx.x;
    int lane = t & 31;
#pragma unroll
    for (int j = 0; j < 16; j++) {
        int row = n0 + j;
        xs[j][t] = (row < n) ? g_x1[(size_t)row * F1 + t] : 0.f;
    }
    __syncthreads();
    int c = t & 31;
    int jg = t >> 5;
    unsigned long long acc2[4] = {0ull, 0ull, 0ull, 0ull};
#pragma unroll 2
    for (int k = 0; k < IN_DIM; k += 4) {
        float w0 = __ldg(&W2[(k + 0) * OUT_D + c]);
        float w1 = __ldg(&W2[(k + 1) * OUT_D + c]);
        float w2 = __ldg(&W2[(k + 2) * OUT_D + c]);
        float w3 = __ldg(&W2[(k + 3) * OUT_D + c]);
        unsigned long long wA = pack2(w0, w1);
        unsigned long long wB = pack2(w2, w3);
#pragma unroll
        for (int q = 0; q < 4; q++) {
            float4 x = *(const float4*)&xs[jg * 4 + q][k];
            ffma2(acc2[q], wA, pack2(x.x, x.y));
            ffma2(acc2[q], wB, pack2(x.z, x.w));
        }
    }
    float av = al[c], rv = ar[c];
#pragma unroll
    for (int q = 0; q < 4; q++) {
        int row = n0 + jg * 4 + q;
        float z = hsum2(acc2[q]);
        if (row < n) g_z2h[(size_t)row * OUT_D + c] = __float2half_rn(z);
        float el = z * av, er = z * rv;
#pragma unroll
        for (int off = 16; off; off >>= 1) {
            el += __shfl_xor_sync(0xffffffffu, el, off);
            er += __shfl_xor_sync(0xffffffffu, er, off);
        }
        if (lane == 0 && row < n) { g_el2[row] = el; g_er2[row] = er; }
    }
}

__global__ void k_aggr2(float* __restrict__ out, const float* __restrict__ b2, int n) {
    int d = blockIdx.x * (blockDim.x >> 5) + (threadIdx.x >> 5);
    if (d >= n) return;
    int lane = threadIdx.x & 31;
    float er = g_er2[d];
    int beg = g_rowstart[d];
    int end = beg + g_cnt[d];
    float acc = 0.f, sacc = 0.f;
    int i = beg;
    for (; i + 3 < end; i += 4) {
        int s0 = g_csrsrc[i],     s1 = g_csrsrc[i + 1];
        int s2 = g_csrsrc[i + 2], s3 = g_csrsrc[i + 3];
        float e0 = g_el2[s0], e1 = g_el2[s1], e2 = g_el2[s2], e3 = g_el2[s3];
        float z0 = __half2float(g_z2h[(size_t)s0 * OUT_D + lane]);
        float z1 = __half2float(g_z2h[(size_t)s1 * OUT_D + lane]);
        float z2 = __half2float(g_z2h[(size_t)s2 * OUT_D + lane]);
        float z3 = __half2float(g_z2h[(size_t)s3 * OUT_D + lane]);
        float x0 = __expf(lrelu(e0 + er));
        float x1 = __expf(lrelu(e1 + er));
        float x2 = __expf(lrelu(e2 + er));
        float x3 = __expf(lrelu(e3 + er));
        sacc += (x0 + x1) + (x2 + x3);
        acc += x0 * z0 + x1 * z1 + x2 * z2 + x3 * z3;
    }
    for (; i < end; i++) {
        int s0 = g_csrsrc[i];
        float x0 = __expf(lrelu(g_el2[s0] + er));
        sacc += x0;
        acc += x0 * __half2float(g_z2h[(size_t)s0 * OUT_D + lane]);
    }
    float inv = (sacc > 0.f) ? __fdividef(1.f, sacc) : 0.f;
    out[(size_t)d * OUT_D + lane] = acc * inv + b2[lane];
}

extern "C" void kernel_launch(void* const* d_in, const int* in_sizes, int n_in,
                              void* d_out, int out_size) {
    const float* h   = (const float*)d_in[0];
    const int*   src = (const int*)d_in[1];
    const int*   dst = (const int*)d_in[2];
    const float* W1  = (const float*)d_in[3];
    const float* al1 = (const float*)d_in[4];
    const float* ar1 = (const float*)d_in[5];
    const float* b1  = (const float*)d_in[6];
    const float* W2  = (const float*)d_in[7];
    const float* al2 = (const float*)d_in[8];
    const float* ar2 = (const float*)d_in[9];
    const float* b2  = (const float*)d_in[10];
    float* out = (float*)d_out;

    int n = in_sizes[0] / IN_DIM;
    int E = in_sizes[1];
    if (n > NMAX) n = NMAX;
    if (E > EMAX) E = EMAX;

    // one-time host resources (no device memory); identical GPU work every call
    static cudaStream_t s2 = nullptr;
    static cudaEvent_t evF = nullptr, evJ = nullptr;
    if (s2 == nullptr) {
        cudaStreamCreateWithFlags(&s2, cudaStreamNonBlocking);
        cudaEventCreateWithFlags(&evF, cudaEventDisableTiming);
        cudaEventCreateWithFlags(&evJ, cudaEventDisableTiming);
    }

    // fork: CSR build on s2, GEMM1 concurrently on main stream
    cudaEventRecord(evF, 0);
    cudaStreamWaitEvent(s2, evF, 0);

    k_zero<<<(n + 255) / 256, 256, 0, s2>>>(n);
    k_hist<<<(E / 4 + 255) / 256, 256, 0, s2>>>(dst, E);
    k_offsets<<<(n + 255) / 256, 256, 0, s2>>>(n);
    k_scatter<<<(E / 4 + 255) / 256, 256, 0, s2>>>(src, dst, E);
    cudaEventRecord(evJ, s2);

    k_gemm1<<<(n + 15) / 16, 128>>>(h, W1, al1, ar1, n);

    // join: aggr1 needs both CSR and gemm1
    cudaStreamWaitEvent(0, evJ, 0);

    k_aggr1<<<(n + 7) / 8, 256>>>(b1, n);
    k_gemm2<<<(n + 15) / 16, 128>>>(W2, al2, ar2, n);
    k_aggr2<<<(n + 7) / 8, 256>>>(out, b2, n);
}

// round 8
// speedup vs baseline: 3.1662x; 1.0001x over previous
#include <cuda_runtime.h>
#include <cuda_fp16.h>
#include <math.h>

#define NMAX 50000
#define EMAX 1600000
#define IN_DIM 128
#define F1 128          // HEADS*HID
#define HEADS 4
#define OUT_D 32

// ---- scratch (static __device__, no allocation) ----
__device__ __half g_z1h[NMAX * F1];          // fp16 layer1 linear output (gather payload)
__device__ float g_el1[NMAX * HEADS];
__device__ float g_er1[NMAX * HEADS];
__device__ float g_x1[NMAX * F1];            // layer1 output (normalized + bias + elu)
__device__ __half g_z2h[NMAX * OUT_D];       // fp16 layer2 linear output
__device__ float g_el2[NMAX];
__device__ float g_er2[NMAX];
// CSR
__device__ int g_cnt[NMAX];
__device__ int g_rowstart[NMAX];
__device__ int g_rank[EMAX];
__device__ int g_csrsrc[EMAX];
__device__ int g_total;

__device__ __forceinline__ float lrelu(float v) { return v > 0.f ? v : 0.2f * v; }
__device__ __forceinline__ float elu1(float v) { return v > 0.f ? v : expm1f(v); }

// ---- packed fp32x2 FMA (SASS FFMA2) ----
__device__ __forceinline__ unsigned long long pack2(float a, float b) {
    unsigned long long r;
    asm("mov.b64 %0, {%1, %2};" : "=l"(r) : "f"(a), "f"(b));
    return r;
}
__device__ __forceinline__ void ffma2(unsigned long long& acc, unsigned long long a,
                                      unsigned long long b) {
    asm("fma.rn.f32x2 %0, %1, %2, %0;" : "+l"(acc) : "l"(a), "l"(b));
}
__device__ __forceinline__ float hsum2(unsigned long long v) {
    float lo, hi;
    asm("mov.b64 {%0, %1}, %2;" : "=f"(lo), "=f"(hi) : "l"(v));
    return lo + hi;
}

// ================= CSR build =================
// hist: 8 edges/thread, records each edge's rank within its dst bucket
__global__ void k_hist(const int* __restrict__ dst, int E) {
    int e = (blockIdx.x * blockDim.x + threadIdx.x) * 8;
    if (e + 7 < E) {
        int4 dA = *(const int4*)&dst[e];
        int4 dB = *(const int4*)&dst[e + 4];
        int4 rA, rB;
        rA.x = atomicAdd(&g_cnt[dA.x], 1);
        rA.y = atomicAdd(&g_cnt[dA.y], 1);
        rA.z = atomicAdd(&g_cnt[dA.z], 1);
        rA.w = atomicAdd(&g_cnt[dA.w], 1);
        rB.x = atomicAdd(&g_cnt[dB.x], 1);
        rB.y = atomicAdd(&g_cnt[dB.y], 1);
        rB.z = atomicAdd(&g_cnt[dB.z], 1);
        rB.w = atomicAdd(&g_cnt[dB.w], 1);
        *(int4*)&g_rank[e] = rA;
        *(int4*)&g_rank[e + 4] = rB;
    } else {
        for (int r = 0; r < 8; r++)
            if (e + r < E) g_rank[e + r] = atomicAdd(&g_cnt[dst[e + r]], 1);
    }
}

// warp-aggregated offsets: shuffle-scan + 1 atomic per warp
__global__ void k_offsets(int n) {
    int i = blockIdx.x * blockDim.x + threadIdx.x;
    int lane = threadIdx.x & 31;
    int c = (i < n) ? g_cnt[i] : 0;
    int inc = c;
#pragma unroll
    for (int off = 1; off < 32; off <<= 1) {
        int v = __shfl_up_sync(0xffffffffu, inc, off);
        if (lane >= off) inc += v;
    }
    int total = __shfl_sync(0xffffffffu, inc, 31);
    int base = 0;
    if (lane == 31) base = atomicAdd(&g_total, total);
    base = __shfl_sync(0xffffffffu, base, 31);
    if (i < n) g_rowstart[i] = base + inc - c;
}

// atomic-free scatter: pos = rowstart[dst] + rank; 8 edges/thread
__global__ void k_scatter(const int* __restrict__ src, const int* __restrict__ dst, int E) {
    int e = (blockIdx.x * blockDim.x + threadIdx.x) * 8;
    if (e + 7 < E) {
        int4 dA = *(const int4*)&dst[e];
        int4 dB = *(const int4*)&dst[e + 4];
        int4 sA = *(const int4*)&src[e];
        int4 sB = *(const int4*)&src[e + 4];
        int4 rA = *(const int4*)&g_rank[e];
        int4 rB = *(const int4*)&g_rank[e + 4];
        int p0 = g_rowstart[dA.x] + rA.x;
        int p1 = g_rowstart[dA.y] + rA.y;
        int p2 = g_rowstart[dA.z] + rA.z;
        int p3 = g_rowstart[dA.w] + rA.w;
        int p4 = g_rowstart[dB.x] + rB.x;
        int p5 = g_rowstart[dB.y] + rB.y;
        int p6 = g_rowstart[dB.z] + rB.z;
        int p7 = g_rowstart[dB.w] + rB.w;
        g_csrsrc[p0] = sA.x;
        g_csrsrc[p1] = sA.y;
        g_csrsrc[p2] = sA.z;
        g_csrsrc[p3] = sA.w;
        g_csrsrc[p4] = sB.x;
        g_csrsrc[p5] = sB.y;
        g_csrsrc[p6] = sB.z;
        g_csrsrc[p7] = sB.w;
    } else {
        for (int r = 0; r < 8; r++) {
            if (e + r < E)
                g_csrsrc[g_rowstart[dst[e + r]] + g_rank[e + r]] = src[e + r];
        }
    }
}

// ================= layer 1 =================
// GEMM1 (16 nodes/block, FFMA2), fused el/er warp-reduction, fp16 z output
__global__ void k_gemm1(const float* __restrict__ h, const float* __restrict__ W1,
                        const float* __restrict__ al, const float* __restrict__ ar, int n) {
    __shared__ float xs[16][IN_DIM];
    int n0 = blockIdx.x * 16;
    int t = threadIdx.x;
    int lane = t & 31;
    int hh = t >> 5;
#pragma unroll
    for (int j = 0; j < 16; j++) {
        int row = n0 + j;
        xs[j][t] = (row < n) ? h[(size_t)row * IN_DIM + t] : 0.f;
    }
    __syncthreads();
    unsigned long long acc2[16];
#pragma unroll
    for (int j = 0; j < 16; j++) acc2[j] = 0ull;
#pragma unroll 2
    for (int k = 0; k < IN_DIM; k += 4) {
        float w0 = __ldg(&W1[(k + 0) * F1 + t]);
        float w1 = __ldg(&W1[(k + 1) * F1 + t]);
        float w2 = __ldg(&W1[(k + 2) * F1 + t]);
        float w3 = __ldg(&W1[(k + 3) * F1 + t]);
        unsigned long long wA = pack2(w0, w1);
        unsigned long long wB = pack2(w2, w3);
#pragma unroll
        for (int j = 0; j < 16; j++) {
            float4 x = *(const float4*)&xs[j][k];
            ffma2(acc2[j], wA, pack2(x.x, x.y));
            ffma2(acc2[j], wB, pack2(x.z, x.w));
        }
    }
    float av = al[t], rv = ar[t];
#pragma unroll
    for (int j = 0; j < 16; j++) {
        int row = n0 + j;
        float z = hsum2(acc2[j]);
        if (row < n) g_z1h[(size_t)row * F1 + t] = __float2half_rn(z);
        float el = z * av, er = z * rv;
#pragma unroll
        for (int off = 16; off; off >>= 1) {
            el += __shfl_xor_sync(0xffffffffu, el, off);
            er += __shfl_xor_sync(0xffffffffu, er, off);
        }
        if (lane == 0 && row < n) {
            g_el1[row * HEADS + hh] = el;
            g_er1[row * HEADS + hh] = er;
        }
    }
}

// aggregation layer1: one warp per dst node; unroll 8 with batched loads
__global__ void k_aggr1(const float* __restrict__ b1, int n) {
    int d = blockIdx.x * (blockDim.x >> 5) + (threadIdx.x >> 5);
    if (d >= n) return;
    int lane = threadIdx.x & 31;
    int hh = lane >> 3;
    float er = g_er1[d * HEADS + hh];
    int beg = g_rowstart[d];
    int end = beg + g_cnt[d];
    float4 acc = make_float4(0.f, 0.f, 0.f, 0.f);
    float sacc = 0.f;
    int i = beg;
    for (; i + 7 < end; i += 8) {
        int s[8];
#pragma unroll
        for (int u = 0; u < 8; u++) s[u] = __ldg(&g_csrsrc[i + u]);
        float ev[8];
        uint2 uz[8];
#pragma unroll
        for (int u = 0; u < 8; u++) {
            ev[u] = __ldg(&g_el1[s[u] * HEADS + hh]);
            uz[u] = *(const uint2*)&g_z1h[(size_t)s[u] * F1 + lane * 4];
        }
#pragma unroll
        for (int u = 0; u < 8; u++) {
            float x = __expf(lrelu(ev[u] + er));
            sacc += x;
            float2 a = __half22float2(*(__half2*)&uz[u].x);
            float2 b = __half22float2(*(__half2*)&uz[u].y);
            acc.x += x * a.x;
            acc.y += x * a.y;
            acc.z += x * b.x;
            acc.w += x * b.y;
        }
    }
    for (; i < end; i++) {
        int s0 = __ldg(&g_csrsrc[i]);
        float e0 = __ldg(&g_el1[s0 * HEADS + hh]);
        uint2 u0 = *(const uint2*)&g_z1h[(size_t)s0 * F1 + lane * 4];
        float x0 = __expf(lrelu(e0 + er));
        sacc += x0;
        float2 a0 = __half22float2(*(__half2*)&u0.x);
        float2 b0 = __half22float2(*(__half2*)&u0.y);
        acc.x += x0 * a0.x; acc.y += x0 * a0.y;
        acc.z += x0 * b0.x; acc.w += x0 * b0.y;
    }
    float inv = (sacc > 0.f) ? __fdividef(1.f, sacc) : 0.f;
    float4 bb = *(const float4*)&b1[lane * 4];
    float4 x;
    x.x = elu1(acc.x * inv + bb.x);
    x.y = elu1(acc.y * inv + bb.y);
    x.z = elu1(acc.z * inv + bb.z);
    x.w = elu1(acc.w * inv + bb.w);
    *(float4*)&g_x1[(size_t)d * F1 + lane * 4] = x;
}

// ================= layer 2 =================
__global__ void k_gemm2(const float* __restrict__ W2, const float* __restrict__ al,
                        const float* __restrict__ ar, int n) {
    __shared__ float xs[16][IN_DIM];
    int n0 = blockIdx.x * 16;
    int t = threadIdx.x;
    int lane = t & 31;
#pragma unroll
    for (int j = 0; j < 16; j++) {
        int row = n0 + j;
        xs[j][t] = (row < n) ? g_x1[(size_t)row * F1 + t] : 0.f;
    }
    __syncthreads();
    int c = t & 31;
    int jg = t >> 5;
    unsigned long long acc2[4] = {0ull, 0ull, 0ull, 0ull};
#pragma unroll 2
    for (int k = 0; k < IN_DIM; k += 4) {
        float w0 = __ldg(&W2[(k + 0) * OUT_D + c]);
        float w1 = __ldg(&W2[(k + 1) * OUT_D + c]);
        float w2 = __ldg(&W2[(k + 2) * OUT_D + c]);
        float w3 = __ldg(&W2[(k + 3) * OUT_D + c]);
        unsigned long long wA = pack2(w0, w1);
        unsigned long long wB = pack2(w2, w3);
#pragma unroll
        for (int q = 0; q < 4; q++) {
            float4 x = *(const float4*)&xs[jg * 4 + q][k];
            ffma2(acc2[q], wA, pack2(x.x, x.y));
            ffma2(acc2[q], wB, pack2(x.z, x.w));
        }
    }
    float av = al[c], rv = ar[c];
#pragma unroll
    for (int q = 0; q < 4; q++) {
        int row = n0 + jg * 4 + q;
        float z = hsum2(acc2[q]);
        if (row < n) g_z2h[(size_t)row * OUT_D + c] = __float2half_rn(z);
        float el = z * av, er = z * rv;
#pragma unroll
        for (int off = 16; off; off >>= 1) {
            el += __shfl_xor_sync(0xffffffffu, el, off);
            er += __shfl_xor_sync(0xffffffffu, er, off);
        }
        if (lane == 0 && row < n) { g_el2[row] = el; g_er2[row] = er; }
    }
}

// aggregation layer2: one warp per dst node; lane = channel; unroll 8
__global__ void k_aggr2(float* __restrict__ out, const float* __restrict__ b2, int n) {
    int d = blockIdx.x * (blockDim.x >> 5) + (threadIdx.x >> 5);
    if (d >= n) return;
    int lane = threadIdx.x & 31;
    float er = g_er2[d];
    int beg = g_rowstart[d];
    int end = beg + g_cnt[d];
    float acc = 0.f, sacc = 0.f;
    int i = beg;
    for (; i + 7 < end; i += 8) {
        int s[8];
#pragma unroll
        for (int u = 0; u < 8; u++) s[u] = __ldg(&g_csrsrc[i + u]);
        float ev[8], zv[8];
#pragma unroll
        for (int u = 0; u < 8; u++) {
            ev[u] = __ldg(&g_el2[s[u]]);
            zv[u] = __half2float(g_z2h[(size_t)s[u] * OUT_D + lane]);
        }
#pragma unroll
        for (int u = 0; u < 8; u++) {
            float x = __expf(lrelu(ev[u] + er));
            sacc += x;
            acc += x * zv[u];
        }
    }
    for (; i < end; i++) {
        int s0 = __ldg(&g_csrsrc[i]);
        float x0 = __expf(lrelu(__ldg(&g_el2[s0]) + er));
        sacc += x0;
        acc += x0 * __half2float(g_z2h[(size_t)s0 * OUT_D + lane]);
    }
    float inv = (sacc > 0.f) ? __fdividef(1.f, sacc) : 0.f;
    out[(size_t)d * OUT_D + lane] = acc * inv + b2[lane];
}

extern "C" void kernel_launch(void* const* d_in, const int* in_sizes, int n_in,
                              void* d_out, int out_size) {
    const float* h   = (const float*)d_in[0];
    const int*   src = (const int*)d_in[1];
    const int*   dst = (const int*)d_in[2];
    const float* W1  = (const float*)d_in[3];
    const float* al1 = (const float*)d_in[4];
    const float* ar1 = (const float*)d_in[5];
    const float* b1  = (const float*)d_in[6];
    const float* W2  = (const float*)d_in[7];
    const float* al2 = (const float*)d_in[8];
    const float* ar2 = (const float*)d_in[9];
    const float* b2  = (const float*)d_in[10];
    float* out = (float*)d_out;

    int n = in_sizes[0] / IN_DIM;
    int E = in_sizes[1];
    if (n > NMAX) n = NMAX;
    if (E > EMAX) E = EMAX;

    // one-time host resources (streams/events + symbol addresses); no device alloc
    static cudaStream_t s2 = nullptr, s3 = nullptr;
    static cudaEvent_t evF = nullptr, evCSR = nullptr, evG1 = nullptr;
    static void* p_cnt = nullptr;
    static void* p_total = nullptr;
    if (s2 == nullptr) {
        cudaStreamCreateWithFlags(&s2, cudaStreamNonBlocking);
        cudaStreamCreateWithFlags(&s3, cudaStreamNonBlocking);
        cudaEventCreateWithFlags(&evF, cudaEventDisableTiming);
        cudaEventCreateWithFlags(&evCSR, cudaEventDisableTiming);
        cudaEventCreateWithFlags(&evG1, cudaEventDisableTiming);
        cudaGetSymbolAddress(&p_cnt, g_cnt);
        cudaGetSymbolAddress(&p_total, g_total);
    }

    // fork: both branches on NON-legacy streams (legacy stream would serialize)
    cudaEventRecord(evF, 0);
    cudaStreamWaitEvent(s2, evF, 0);
    cudaStreamWaitEvent(s3, evF, 0);

    // branch A (s2): CSR build
    cudaMemsetAsync(p_cnt, 0, (size_t)n * sizeof(int), s2);
    cudaMemsetAsync(p_total, 0, sizeof(int), s2);
    k_hist<<<(E / 8 + 255) / 256, 256, 0, s2>>>(dst, E);
    k_offsets<<<(n + 255) / 256, 256, 0, s2>>>(n);
    k_scatter<<<(E / 8 + 255) / 256, 256, 0, s2>>>(src, dst, E);
    cudaEventRecord(evCSR, s2);

    // branch B (s3): GEMM1 + fused attention coefficients
    k_gemm1<<<(n + 15) / 16, 128, 0, s3>>>(h, W1, al1, ar1, n);
    cudaEventRecord(evG1, s3);

    // join onto capture stream
    cudaStreamWaitEvent(0, evCSR, 0);
    cudaStreamWaitEvent(0, evG1, 0);

    k_aggr1<<<(n + 7) / 8, 256>>>(b1, n);
    k_gemm2<<<(n + 15) / 16, 128>>>(W2, al2, ar2, n);
    k_aggr2<<<(n + 7) / 8, 256>>>(out, b2, n);
}